// round 3
// baseline (speedup 1.0000x reference)
#include <cuda_runtime.h>

#define NT 256
#define RPT 2
#define STEPS 15
#define SPEED 5.0f
#define NCOLS_IN 18
#define NCOLS_OUT 178

__global__ void __launch_bounds__(NT) prog_kernel(
    const float* __restrict__ x,
    const float* __restrict__ c1w, const float* __restrict__ c1b,
    const float* __restrict__ c2w, const float* __restrict__ c2b,
    const float* __restrict__ l1w, const float* __restrict__ l1b,
    const float* __restrict__ l2w, const float* __restrict__ l2b,
    float* __restrict__ out, int n)
{
    // Packed per-neuron weight block, stride 12 floats (48B, 16B-aligned):
    //  [0..3] l1w[0..3][j] (transposed), [4] l1b[j], [5..9] l2w[j][0..4]
    __shared__ float s_w[32 * 12];
    __shared__ float s_cb[12];

    const int t = threadIdx.x;
    if (t < 32) {
        const int j = t;
        s_w[12 * j + 0] = l1w[0 * 32 + j];
        s_w[12 * j + 1] = l1w[1 * 32 + j];
        s_w[12 * j + 2] = l1w[2 * 32 + j];
        s_w[12 * j + 3] = l1w[3 * 32 + j];
        s_w[12 * j + 4] = l1b[j];
        s_w[12 * j + 5] = l2w[5 * j + 0];
        s_w[12 * j + 6] = l2w[5 * j + 1];
        s_w[12 * j + 7] = l2w[5 * j + 2];
        s_w[12 * j + 8] = l2w[5 * j + 3];
        s_w[12 * j + 9] = l2w[5 * j + 4];
        s_w[12 * j + 10] = 0.0f;
        s_w[12 * j + 11] = 0.0f;
    } else if (t < 64) {
        const int u = t - 32;
        if (u < 12) {
            float v;
            if      (u == 0) v = c1w[0];
            else if (u == 1) v = c1w[1];
            else if (u == 2) v = c1b[0];
            else if (u == 3) v = c2w[0];
            else if (u == 4) v = c2w[1];
            else if (u == 5) v = c2b[0];
            else if (u < 11) v = l2b[u - 6];
            else             v = 0.0f;
            s_cb[u] = v;
        }
    }
    __syncthreads();

    const float c1w0 = s_cb[0], c1w1 = s_cb[1], c1b0 = s_cb[2];
    const float c2w0 = s_cb[3], c2w1 = s_cb[4], c2b0 = s_cb[5];
    const float l2b0 = s_cb[6], l2b1 = s_cb[7], l2b2 = s_cb[8];
    const float l2b3 = s_cb[9], l2b4 = s_cb[10];

    const int row0 = blockIdx.x * (NT * RPT) + t;

    // per-row state, two independent rows for ILP
    float s0[RPT], s1[RPT], s2[RPT], s3[RPT], s4[RPT], s5[RPT], s6[RPT],
          s7[RPT], s8[RPT], s9[RPT], s10[RPT], s11[RPT], s12[RPT], s13[RPT],
          s14[RPT], s15[RPT], s16[RPT], s17[RPT];
    bool act[RPT];
    float* orow[RPT];

    #pragma unroll
    for (int r = 0; r < RPT; r++) {
        const int row = row0 + r * NT;
        act[r] = (row < n);
        const int rr = act[r] ? row : 0;
        const float* xr = x + (long long)rr * NCOLS_IN;
        orow[r] = out + (long long)rr * NCOLS_OUT;
        float2 v0 = *(const float2*)(xr + 0);
        float2 v1 = *(const float2*)(xr + 2);
        float2 v2 = *(const float2*)(xr + 4);
        float2 v3 = *(const float2*)(xr + 6);
        float2 v4 = *(const float2*)(xr + 8);
        float2 v8 = *(const float2*)(xr + 16);
        s0[r] = v0.x; s1[r] = v0.y; s2[r] = v1.x; s3[r] = v1.y;
        s4[r] = v2.x; s5[r] = v2.y; s6[r] = v3.x; s7[r] = v3.y;
        s8[r] = v4.x; s9[r] = v4.y; s17[r] = v8.y;
        float d13 = s1[r] - s3[r], d24 = s2[r] - s4[r];
        s10[r] = fmaf(d13, d13, d24 * d24);
        s11[r] = s12[r] = s13[r] = s14[r] = s15[r] = s16[r] = 0.0f;
        if (act[r]) {
            float* o = orow[r] + 18;
            *(float2*)(o + 0) = make_float2(s10[r], s1[r]);
            *(float2*)(o + 2) = make_float2(s2[r], s3[r]);
            *(float2*)(o + 4) = make_float2(s4[r], s5[r]);
            *(float2*)(o + 6) = make_float2(s6[r], s7[r]);
            *(float2*)(o + 8) = make_float2(s8[r], s17[r]);
        }
    }

    #pragma unroll 1
    for (int step = 0; step < STEPS; step++) {
        float h20[RPT], h21[RPT], h22[RPT], h23[RPT];
        float p0[RPT], p1[RPT], p2[RPT], p3[RPT], p4[RPT];

        #pragma unroll
        for (int r = 0; r < RPT; r++) {
            const float f0 = s1[r], f1 = s2[r], f2 = s3[r], f3 = s4[r],
                        f4 = s9[r], f5 = s17[r];
            float h10 = fmaxf(fmaf(c1w1, f1, fmaf(c1w0, f0, c1b0)), 0.0f);
            float h11 = fmaxf(fmaf(c1w1, f2, fmaf(c1w0, f1, c1b0)), 0.0f);
            float h12 = fmaxf(fmaf(c1w1, f3, fmaf(c1w0, f2, c1b0)), 0.0f);
            float h13 = fmaxf(fmaf(c1w1, f4, fmaf(c1w0, f3, c1b0)), 0.0f);
            float h14 = fmaxf(fmaf(c1w1, f5, fmaf(c1w0, f4, c1b0)), 0.0f);
            h20[r] = fmaxf(fmaf(c2w1, h11, fmaf(c2w0, h10, c2b0)), 0.0f);
            h21[r] = fmaxf(fmaf(c2w1, h12, fmaf(c2w0, h11, c2b0)), 0.0f);
            h22[r] = fmaxf(fmaf(c2w1, h13, fmaf(c2w0, h12, c2b0)), 0.0f);
            h23[r] = fmaxf(fmaf(c2w1, h14, fmaf(c2w0, h13, c2b0)), 0.0f);
            p0[r] = l2b0; p1[r] = l2b1; p2[r] = l2b2; p3[r] = l2b3; p4[r] = l2b4;
        }

        #pragma unroll
        for (int j = 0; j < 32; j++) {
            const float4 wa = *(const float4*)(s_w + 12 * j + 0);
            const float4 wb = *(const float4*)(s_w + 12 * j + 4);
            const float2 wc = *(const float2*)(s_w + 12 * j + 8);
            #pragma unroll
            for (int r = 0; r < RPT; r++) {
                float h3 = fmaf(h23[r], wa.w,
                           fmaf(h22[r], wa.z,
                           fmaf(h21[r], wa.y,
                           fmaf(h20[r], wa.x, wb.x))));
                h3 = fmaxf(h3, 0.0f);
                p0[r] = fmaf(h3, wb.y, p0[r]);
                p1[r] = fmaf(h3, wb.z, p1[r]);
                p2[r] = fmaf(h3, wb.w, p2[r]);
                p3[r] = fmaf(h3, wc.x, p3[r]);
                p4[r] = fmaf(h3, wc.y, p4[r]);
            }
        }

        #pragma unroll
        for (int r = 0; r < RPT; r++) {
            // sigmoid, full precision
            float q0 = 1.0f / (1.0f + expf(-p0[r]));
            float q1 = 1.0f / (1.0f + expf(-p1[r]));
            float q2 = 1.0f / (1.0f + expf(-p2[r]));
            float q3 = 1.0f / (1.0f + expf(-p3[r]));
            float q4 = 1.0f / (1.0f + expf(-p4[r]));

            s5[r] = q0; s6[r] = q1; s7[r] = q2; s8[r] = q3; s17[r] = q4;

            const float a = q1 - q0, b = q2 - q0, c = q3 - q0;
            const float d = q2 - q1, e = q3 - q1, f = q3 - q2;
            s11[r] = a; s12[r] = b; s13[r] = c;
            s14[r] = d; s15[r] = e; s16[r] = f;

            const float dx_c = (c <= 0.0f) ? 0.0f : SPEED;
            const float st_c = (c <= 0.0f) ? 0.0f : 3.0f;
            const float dx_f = (f <= 0.0f) ? 0.0f : SPEED;
            const float st_f = (f <= 0.0f) ? 2.0f : 3.0f;
            const float dx_e = (e <= 0.0f) ? -SPEED : SPEED;
            const float st_e = (e <= 0.0f) ? 1.0f : 3.0f;
            const float dx_b = (b <= 0.0f) ? dx_c : dx_f;
            const float st_b = (b <= 0.0f) ? st_c : st_f;
            const float dx_d = (d <= 0.0f) ? dx_e : dx_f;
            const float st_d = (d <= 0.0f) ? st_e : st_f;
            const float dx   = (a <= 0.0f) ? dx_b : dx_d;
            const float st   = (a <= 0.0f) ? st_b : st_d;

            s1[r] += dx;
            s9[r] = st;
            s2[r] += SPEED;
            s3[r] += SPEED;
            s0[r] += 1.0f;
            float d13 = s1[r] - s3[r], d24 = s2[r] - s4[r];
            s10[r] = fmaf(d13, d13, d24 * d24);

            if (act[r]) {
                float* o = orow[r] + 18 + 10 * (step + 1);
                *(float2*)(o + 0) = make_float2(s10[r], s1[r]);
                *(float2*)(o + 2) = make_float2(s2[r], s3[r]);
                *(float2*)(o + 4) = make_float2(s4[r], s5[r]);
                *(float2*)(o + 6) = make_float2(s6[r], s7[r]);
                *(float2*)(o + 8) = make_float2(s8[r], s17[r]);
            }
        }
    }

    #pragma unroll
    for (int r = 0; r < RPT; r++) {
        if (!act[r]) continue;
        float* o = orow[r];
        *(float2*)(o + 0)  = make_float2(s0[r], s1[r]);
        *(float2*)(o + 2)  = make_float2(s2[r], s3[r]);
        *(float2*)(o + 4)  = make_float2(s4[r], s5[r]);
        *(float2*)(o + 6)  = make_float2(s6[r], s7[r]);
        *(float2*)(o + 8)  = make_float2(s8[r], s9[r]);
        *(float2*)(o + 10) = make_float2(s10[r], s11[r]);
        *(float2*)(o + 12) = make_float2(s12[r], s13[r]);
        *(float2*)(o + 14) = make_float2(s14[r], s15[r]);
        *(float2*)(o + 16) = make_float2(s16[r], s17[r]);
    }
}

extern "C" void kernel_launch(void* const* d_in, const int* in_sizes, int n_in,
                              void* d_out, int out_size)
{
    const float* x   = (const float*)d_in[0];
    const float* c1w = (const float*)d_in[1];
    const float* c1b = (const float*)d_in[2];
    const float* c2w = (const float*)d_in[3];
    const float* c2b = (const float*)d_in[4];
    const float* l1w = (const float*)d_in[5];
    const float* l1b = (const float*)d_in[6];
    const float* l2w = (const float*)d_in[7];
    const float* l2b = (const float*)d_in[8];
    float* out = (float*)d_out;

    const int n = in_sizes[0] / NCOLS_IN;
    const int rows_per_block = NT * RPT;
    const int blocks = (n + rows_per_block - 1) / rows_per_block;
    prog_kernel<<<blocks, NT>>>(x, c1w, c1b, c2w, c2b, l1w, l1b, l2w, l2b, out, n);
}

// round 4
// speedup vs baseline: 1.5874x; 1.5874x over previous
#include <cuda_runtime.h>

#define NT 128
#define STEPS 15
#define SPEED 5.0f
#define NCOLS_IN 18
#define NCOLS_OUT 178

__global__ void __launch_bounds__(NT, 4) prog_kernel(
    const float* __restrict__ x,
    const float* __restrict__ c1w, const float* __restrict__ c1b,
    const float* __restrict__ c2w, const float* __restrict__ c2b,
    const float* __restrict__ l1w, const float* __restrict__ l1b,
    const float* __restrict__ l2w, const float* __restrict__ l2b,
    float* __restrict__ out, int n)
{
    // Packed per-neuron weight block, stride 12 floats (48B, 16B-aligned):
    //  [0..3] l1w[0..3][j] (transposed), [4] l1b[j], [5..9] l2w[j][0..4]
    // All lanes read the same j -> broadcast, conflict-free.
    __shared__ float s_w[32 * 12];
    __shared__ float s_cb[12];

    const int t = threadIdx.x;
    if (t < 32) {
        const int j = t;
        s_w[12 * j + 0] = l1w[0 * 32 + j];
        s_w[12 * j + 1] = l1w[1 * 32 + j];
        s_w[12 * j + 2] = l1w[2 * 32 + j];
        s_w[12 * j + 3] = l1w[3 * 32 + j];
        s_w[12 * j + 4] = l1b[j];
        s_w[12 * j + 5] = l2w[5 * j + 0];
        s_w[12 * j + 6] = l2w[5 * j + 1];
        s_w[12 * j + 7] = l2w[5 * j + 2];
        s_w[12 * j + 8] = l2w[5 * j + 3];
        s_w[12 * j + 9] = l2w[5 * j + 4];
        s_w[12 * j + 10] = 0.0f;
        s_w[12 * j + 11] = 0.0f;
    } else if (t < 64) {
        const int u = t - 32;
        if (u < 12) {
            float v;
            if      (u == 0) v = c1w[0];
            else if (u == 1) v = c1w[1];
            else if (u == 2) v = c1b[0];
            else if (u == 3) v = c2w[0];
            else if (u == 4) v = c2w[1];
            else if (u == 5) v = c2b[0];
            else if (u < 11) v = l2b[u - 6];
            else             v = 0.0f;
            s_cb[u] = v;
        }
    }
    __syncthreads();

    const int row = blockIdx.x * NT + t;
    if (row >= n) return;

    const float c1w0 = s_cb[0], c1w1 = s_cb[1], c1b0 = s_cb[2];
    const float c2w0 = s_cb[3], c2w1 = s_cb[4], c2b0 = s_cb[5];
    const float l2b0 = s_cb[6], l2b1 = s_cb[7], l2b2 = s_cb[8];
    const float l2b3 = s_cb[9], l2b4 = s_cb[10];

    // ---- load state row (18 floats, 8B-aligned) ----
    const float* xr = x + (long long)row * NCOLS_IN;
    float2 v0 = *(const float2*)(xr + 0);
    float2 v1 = *(const float2*)(xr + 2);
    float2 v2 = *(const float2*)(xr + 4);
    float2 v3 = *(const float2*)(xr + 6);
    float2 v4 = *(const float2*)(xr + 8);
    float2 v8 = *(const float2*)(xr + 16);
    float s0 = v0.x, s1 = v0.y, s2 = v1.x, s3 = v1.y;
    float s4 = v2.x, s5 = v2.y, s6 = v3.x, s7 = v3.y;
    float s8 = v4.x, s9 = v4.y, s10;
    float s11 = 0.0f, s12 = 0.0f, s13 = 0.0f, s14 = 0.0f, s15 = 0.0f, s16 = 0.0f;
    float s17 = v8.y;

    {
        float d13 = s1 - s3, d24 = s2 - s4;
        s10 = fmaf(d13, d13, d24 * d24);
    }

    float* orow = out + (long long)row * NCOLS_OUT;

    // traj0 = s[10,1,2,3,4,5,6,7,8,17] at columns [18,28)
    {
        float* o = orow + 18;
        *(float2*)(o + 0) = make_float2(s10, s1);
        *(float2*)(o + 2) = make_float2(s2, s3);
        *(float2*)(o + 4) = make_float2(s4, s5);
        *(float2*)(o + 6) = make_float2(s6, s7);
        *(float2*)(o + 8) = make_float2(s8, s17);
    }

    #pragma unroll 1
    for (int step = 0; step < STEPS; step++) {
        // feat = s[1,2,3,4,9,17]
        const float f0 = s1, f1 = s2, f2 = s3, f3 = s4, f4 = s9, f5 = s17;

        float h10 = fmaxf(fmaf(c1w1, f1, fmaf(c1w0, f0, c1b0)), 0.0f);
        float h11 = fmaxf(fmaf(c1w1, f2, fmaf(c1w0, f1, c1b0)), 0.0f);
        float h12 = fmaxf(fmaf(c1w1, f3, fmaf(c1w0, f2, c1b0)), 0.0f);
        float h13 = fmaxf(fmaf(c1w1, f4, fmaf(c1w0, f3, c1b0)), 0.0f);
        float h14 = fmaxf(fmaf(c1w1, f5, fmaf(c1w0, f4, c1b0)), 0.0f);

        float h20 = fmaxf(fmaf(c2w1, h11, fmaf(c2w0, h10, c2b0)), 0.0f);
        float h21 = fmaxf(fmaf(c2w1, h12, fmaf(c2w0, h11, c2b0)), 0.0f);
        float h22 = fmaxf(fmaf(c2w1, h13, fmaf(c2w0, h12, c2b0)), 0.0f);
        float h23 = fmaxf(fmaf(c2w1, h14, fmaf(c2w0, h13, c2b0)), 0.0f);

        float p0 = l2b0, p1 = l2b1, p2 = l2b2, p3 = l2b3, p4 = l2b4;

        // Partial unroll: bounded LDS prefetch window -> bounded reg demand.
        #pragma unroll 4
        for (int j = 0; j < 32; j++) {
            const float4 wa = *(const float4*)(s_w + 12 * j + 0);
            const float4 wb = *(const float4*)(s_w + 12 * j + 4);
            const float2 wc = *(const float2*)(s_w + 12 * j + 8);
            float h3 = fmaf(h23, wa.w,
                       fmaf(h22, wa.z,
                       fmaf(h21, wa.y,
                       fmaf(h20, wa.x, wb.x))));
            h3 = fmaxf(h3, 0.0f);
            p0 = fmaf(h3, wb.y, p0);
            p1 = fmaf(h3, wb.z, p1);
            p2 = fmaf(h3, wb.w, p2);
            p3 = fmaf(h3, wc.x, p3);
            p4 = fmaf(h3, wc.y, p4);
        }

        // sigmoid, full precision
        p0 = 1.0f / (1.0f + expf(-p0));
        p1 = 1.0f / (1.0f + expf(-p1));
        p2 = 1.0f / (1.0f + expf(-p2));
        p3 = 1.0f / (1.0f + expf(-p3));
        p4 = 1.0f / (1.0f + expf(-p4));

        s5 = p0; s6 = p1; s7 = p2; s8 = p3; s17 = p4;

        const float a = p1 - p0, b = p2 - p0, c = p3 - p0;
        const float d = p2 - p1, e = p3 - p1, f = p3 - p2;
        s11 = a; s12 = b; s13 = c; s14 = d; s15 = e; s16 = f;

        const float dx_c = (c <= 0.0f) ? 0.0f : SPEED;
        const float st_c = (c <= 0.0f) ? 0.0f : 3.0f;
        const float dx_f = (f <= 0.0f) ? 0.0f : SPEED;
        const float st_f = (f <= 0.0f) ? 2.0f : 3.0f;
        const float dx_e = (e <= 0.0f) ? -SPEED : SPEED;
        const float st_e = (e <= 0.0f) ? 1.0f : 3.0f;
        const float dx_b = (b <= 0.0f) ? dx_c : dx_f;
        const float st_b = (b <= 0.0f) ? st_c : st_f;
        const float dx_d = (d <= 0.0f) ? dx_e : dx_f;
        const float st_d = (d <= 0.0f) ? st_e : st_f;
        const float dx   = (a <= 0.0f) ? dx_b : dx_d;
        const float st   = (a <= 0.0f) ? st_b : st_d;

        s1 += dx;
        s9 = st;
        s2 += SPEED;
        s3 += SPEED;
        s0 += 1.0f;
        {
            float d13 = s1 - s3, d24 = s2 - s4;
            s10 = fmaf(d13, d13, d24 * d24);
        }

        float* o = orow + 18 + 10 * (step + 1);
        *(float2*)(o + 0) = make_float2(s10, s1);
        *(float2*)(o + 2) = make_float2(s2, s3);
        *(float2*)(o + 4) = make_float2(s4, s5);
        *(float2*)(o + 6) = make_float2(s6, s7);
        *(float2*)(o + 8) = make_float2(s8, s17);
    }

    // final state -> columns [0,18)
    *(float2*)(orow + 0)  = make_float2(s0, s1);
    *(float2*)(orow + 2)  = make_float2(s2, s3);
    *(float2*)(orow + 4)  = make_float2(s4, s5);
    *(float2*)(orow + 6)  = make_float2(s6, s7);
    *(float2*)(orow + 8)  = make_float2(s8, s9);
    *(float2*)(orow + 10) = make_float2(s10, s11);
    *(float2*)(orow + 12) = make_float2(s12, s13);
    *(float2*)(orow + 14) = make_float2(s14, s15);
    *(float2*)(orow + 16) = make_float2(s16, s17);
}

extern "C" void kernel_launch(void* const* d_in, const int* in_sizes, int n_in,
                              void* d_out, int out_size)
{
    const float* x   = (const float*)d_in[0];
    const float* c1w = (const float*)d_in[1];
    const float* c1b = (const float*)d_in[2];
    const float* c2w = (const float*)d_in[3];
    const float* c2b = (const float*)d_in[4];
    const float* l1w = (const float*)d_in[5];
    const float* l1b = (const float*)d_in[6];
    const float* l2w = (const float*)d_in[7];
    const float* l2b = (const float*)d_in[8];
    float* out = (float*)d_out;

    const int n = in_sizes[0] / NCOLS_IN;
    const int blocks = (n + NT - 1) / NT;
    prog_kernel<<<blocks, NT>>>(x, c1w, c1b, c2w, c2b, l1w, l1b, l2w, l2b, out, n);
}

// round 5
// speedup vs baseline: 2.0407x; 1.2856x over previous
#include <cuda_runtime.h>

#define NT 128
#define STEPS 15
#define SPEED 5.0f
#define NCOLS_IN 18
#define NCOLS_OUT 178
#define ROW_PAD 179            // SMEM row stride (odd -> conflict-free)
#define SMEM_BYTES (NT * ROW_PAD * 4)

__global__ void __launch_bounds__(NT) prog_kernel(
    const float* __restrict__ x,
    const float* __restrict__ c1w, const float* __restrict__ c1b,
    const float* __restrict__ c2w, const float* __restrict__ c2b,
    const float* __restrict__ l1w, const float* __restrict__ l1b,
    const float* __restrict__ l2w, const float* __restrict__ l2b,
    float* __restrict__ out, int n)
{
    // Dynamic SMEM: per-thread staged output row (178 cols, stride 179).
    extern __shared__ float s_rows[];

    // Packed per-neuron weight block, stride 12 floats (48B, 16B-aligned):
    //  [0..3] l1w[0..3][j] (transposed), [4] l1b[j], [5..9] l2w[j][0..4]
    __shared__ float s_w[32 * 12];
    __shared__ float s_cb[12];

    const int t = threadIdx.x;
    if (t < 32) {
        const int j = t;
        s_w[12 * j + 0] = l1w[0 * 32 + j];
        s_w[12 * j + 1] = l1w[1 * 32 + j];
        s_w[12 * j + 2] = l1w[2 * 32 + j];
        s_w[12 * j + 3] = l1w[3 * 32 + j];
        s_w[12 * j + 4] = l1b[j];
        s_w[12 * j + 5] = l2w[5 * j + 0];
        s_w[12 * j + 6] = l2w[5 * j + 1];
        s_w[12 * j + 7] = l2w[5 * j + 2];
        s_w[12 * j + 8] = l2w[5 * j + 3];
        s_w[12 * j + 9] = l2w[5 * j + 4];
        s_w[12 * j + 10] = 0.0f;
        s_w[12 * j + 11] = 0.0f;
    } else if (t < 64) {
        const int u = t - 32;
        if (u < 12) {
            float v;
            if      (u == 0) v = c1w[0];
            else if (u == 1) v = c1w[1];
            else if (u == 2) v = c1b[0];
            else if (u == 3) v = c2w[0];
            else if (u == 4) v = c2w[1];
            else if (u == 5) v = c2b[0];
            else if (u < 11) v = l2b[u - 6];
            else             v = 0.0f;
            s_cb[u] = v;
        }
    }
    __syncthreads();

    const int R0 = blockIdx.x * NT;
    const int rows_blk = (n - R0 < NT) ? (n - R0) : NT;
    const bool act = (t < rows_blk);

    if (act) {
        const int row = R0 + t;
        const float c1w0 = s_cb[0], c1w1 = s_cb[1], c1b0 = s_cb[2];
        const float c2w0 = s_cb[3], c2w1 = s_cb[4], c2b0 = s_cb[5];
        const float l2b0 = s_cb[6], l2b1 = s_cb[7], l2b2 = s_cb[8];
        const float l2b3 = s_cb[9], l2b4 = s_cb[10];

        float* my = s_rows + t * ROW_PAD;

        // ---- load state row (18 floats, 8B-aligned) ----
        const float* xr = x + (long long)row * NCOLS_IN;
        float2 v0 = *(const float2*)(xr + 0);
        float2 v1 = *(const float2*)(xr + 2);
        float2 v2 = *(const float2*)(xr + 4);
        float2 v3 = *(const float2*)(xr + 6);
        float2 v4 = *(const float2*)(xr + 8);
        float2 v8 = *(const float2*)(xr + 16);
        float s0 = v0.x, s1 = v0.y, s2 = v1.x, s3 = v1.y;
        float s4 = v2.x, s5 = v2.y, s6 = v3.x, s7 = v3.y;
        float s8 = v4.x, s9 = v4.y, s10;
        float s11 = 0.0f, s12 = 0.0f, s13 = 0.0f, s14 = 0.0f, s15 = 0.0f, s16 = 0.0f;
        float s17 = v8.y;

        {
            float d13 = s1 - s3, d24 = s2 - s4;
            s10 = fmaf(d13, d13, d24 * d24);
        }

        // traj0 -> staged cols [18,28)
        my[18] = s10; my[19] = s1; my[20] = s2; my[21] = s3; my[22] = s4;
        my[23] = s5;  my[24] = s6; my[25] = s7; my[26] = s8; my[27] = s17;

        #pragma unroll 1
        for (int step = 0; step < STEPS; step++) {
            const float f0 = s1, f1 = s2, f2 = s3, f3 = s4, f4 = s9, f5 = s17;

            float h10 = fmaxf(fmaf(c1w1, f1, fmaf(c1w0, f0, c1b0)), 0.0f);
            float h11 = fmaxf(fmaf(c1w1, f2, fmaf(c1w0, f1, c1b0)), 0.0f);
            float h12 = fmaxf(fmaf(c1w1, f3, fmaf(c1w0, f2, c1b0)), 0.0f);
            float h13 = fmaxf(fmaf(c1w1, f4, fmaf(c1w0, f3, c1b0)), 0.0f);
            float h14 = fmaxf(fmaf(c1w1, f5, fmaf(c1w0, f4, c1b0)), 0.0f);

            float h20 = fmaxf(fmaf(c2w1, h11, fmaf(c2w0, h10, c2b0)), 0.0f);
            float h21 = fmaxf(fmaf(c2w1, h12, fmaf(c2w0, h11, c2b0)), 0.0f);
            float h22 = fmaxf(fmaf(c2w1, h13, fmaf(c2w0, h12, c2b0)), 0.0f);
            float h23 = fmaxf(fmaf(c2w1, h14, fmaf(c2w0, h13, c2b0)), 0.0f);

            float p0 = l2b0, p1 = l2b1, p2 = l2b2, p3 = l2b3, p4 = l2b4;

            #pragma unroll 8
            for (int j = 0; j < 32; j++) {
                const float4 wa = *(const float4*)(s_w + 12 * j + 0);
                const float4 wb = *(const float4*)(s_w + 12 * j + 4);
                const float2 wc = *(const float2*)(s_w + 12 * j + 8);
                float h3 = fmaf(h23, wa.w,
                           fmaf(h22, wa.z,
                           fmaf(h21, wa.y,
                           fmaf(h20, wa.x, wb.x))));
                h3 = fmaxf(h3, 0.0f);
                p0 = fmaf(h3, wb.y, p0);
                p1 = fmaf(h3, wb.z, p1);
                p2 = fmaf(h3, wb.w, p2);
                p3 = fmaf(h3, wc.x, p3);
                p4 = fmaf(h3, wc.y, p4);
            }

            // sigmoid, full precision
            p0 = 1.0f / (1.0f + expf(-p0));
            p1 = 1.0f / (1.0f + expf(-p1));
            p2 = 1.0f / (1.0f + expf(-p2));
            p3 = 1.0f / (1.0f + expf(-p3));
            p4 = 1.0f / (1.0f + expf(-p4));

            s5 = p0; s6 = p1; s7 = p2; s8 = p3; s17 = p4;

            const float a = p1 - p0, b = p2 - p0, c = p3 - p0;
            const float d = p2 - p1, e = p3 - p1, f = p3 - p2;
            s11 = a; s12 = b; s13 = c; s14 = d; s15 = e; s16 = f;

            const float dx_c = (c <= 0.0f) ? 0.0f : SPEED;
            const float st_c = (c <= 0.0f) ? 0.0f : 3.0f;
            const float dx_f = (f <= 0.0f) ? 0.0f : SPEED;
            const float st_f = (f <= 0.0f) ? 2.0f : 3.0f;
            const float dx_e = (e <= 0.0f) ? -SPEED : SPEED;
            const float st_e = (e <= 0.0f) ? 1.0f : 3.0f;
            const float dx_b = (b <= 0.0f) ? dx_c : dx_f;
            const float st_b = (b <= 0.0f) ? st_c : st_f;
            const float dx_d = (d <= 0.0f) ? dx_e : dx_f;
            const float st_d = (d <= 0.0f) ? st_e : st_f;
            const float dx   = (a <= 0.0f) ? dx_b : dx_d;
            const float st   = (a <= 0.0f) ? st_b : st_d;

            s1 += dx;
            s9 = st;
            s2 += SPEED;
            s3 += SPEED;
            s0 += 1.0f;
            {
                float d13 = s1 - s3, d24 = s2 - s4;
                s10 = fmaf(d13, d13, d24 * d24);
            }

            // staged traj: cols [18 + 10*(step+1), +10)
            float* o = my + 18 + 10 * (step + 1);
            o[0] = s10; o[1] = s1; o[2] = s2; o[3] = s3; o[4] = s4;
            o[5] = s5;  o[6] = s6; o[7] = s7; o[8] = s8; o[9] = s17;
        }

        // final state -> staged cols [0,18)
        my[0] = s0;  my[1] = s1;  my[2] = s2;  my[3] = s3;
        my[4] = s4;  my[5] = s5;  my[6] = s6;  my[7] = s7;
        my[8] = s8;  my[9] = s9;  my[10] = s10; my[11] = s11;
        my[12] = s12; my[13] = s13; my[14] = s14; my[15] = s15;
        my[16] = s16; my[17] = s17;
    }

    __syncthreads();

    // Coalesced flush: CTA's rows form one contiguous output region.
    {
        float* obase = out + (long long)R0 * NCOLS_OUT;
        const unsigned total = (unsigned)rows_blk * NCOLS_OUT;
        for (unsigned idx = t; idx < total; idx += NT) {
            unsigned r = idx / NCOLS_OUT;
            unsigned c = idx - r * NCOLS_OUT;
            obase[idx] = s_rows[r * ROW_PAD + c];
        }
    }
}

extern "C" void kernel_launch(void* const* d_in, const int* in_sizes, int n_in,
                              void* d_out, int out_size)
{
    const float* x   = (const float*)d_in[0];
    const float* c1w = (const float*)d_in[1];
    const float* c1b = (const float*)d_in[2];
    const float* c2w = (const float*)d_in[3];
    const float* c2b = (const float*)d_in[4];
    const float* l1w = (const float*)d_in[5];
    const float* l1b = (const float*)d_in[6];
    const float* l2w = (const float*)d_in[7];
    const float* l2b = (const float*)d_in[8];
    float* out = (float*)d_out;

    cudaFuncSetAttribute(prog_kernel,
                         cudaFuncAttributeMaxDynamicSharedMemorySize, SMEM_BYTES);

    const int n = in_sizes[0] / NCOLS_IN;
    const int blocks = (n + NT - 1) / NT;
    prog_kernel<<<blocks, NT, SMEM_BYTES>>>(x, c1w, c1b, c2w, c2b,
                                            l1w, l1b, l2w, l2b, out, n);
}

// round 6
// speedup vs baseline: 2.9540x; 1.4475x over previous
#include <cuda_runtime.h>

#define NT 128
#define STEPS 15
#define SPEED 5.0f
#define NCOLS_IN 18
#define NCOLS_OUT 178
#define CB 61                   // staged cols per phase (60) + 1 pad (odd stride)
#define SMEM_BYTES (NT * CB * 4)

__device__ __forceinline__ void flush_seg(float* __restrict__ out,
                                          const float* __restrict__ stage,
                                          int R0, int rows_blk, int base_col,
                                          int ncols, int t)
{
    // out[(R0+r)*178 + base_col + c] = stage[r*CB + c]; coalesced in idx.
    const unsigned total = (unsigned)rows_blk * ncols;
    for (unsigned idx = t; idx < total; idx += NT) {
        unsigned r = idx / ncols;
        unsigned c = idx - r * ncols;
        out[(long long)(R0 + r) * NCOLS_OUT + base_col + c] = stage[r * CB + c];
    }
}

__global__ void __launch_bounds__(NT) prog_kernel(
    const float* __restrict__ x,
    const float* __restrict__ c1w, const float* __restrict__ c1b,
    const float* __restrict__ c2w, const float* __restrict__ c2b,
    const float* __restrict__ l1w, const float* __restrict__ l1b,
    const float* __restrict__ l2w, const float* __restrict__ l2b,
    float* __restrict__ out, int n)
{
    extern __shared__ float s_rows[];   // NT * CB staging

    // Packed per-neuron weights, stride 12: [0..3] l1w^T, [4] l1b, [5..9] l2w
    __shared__ float s_w[32 * 12];
    __shared__ float s_cb[12];

    const int t = threadIdx.x;
    if (t < 32) {
        const int j = t;
        s_w[12 * j + 0] = l1w[0 * 32 + j];
        s_w[12 * j + 1] = l1w[1 * 32 + j];
        s_w[12 * j + 2] = l1w[2 * 32 + j];
        s_w[12 * j + 3] = l1w[3 * 32 + j];
        s_w[12 * j + 4] = l1b[j];
        s_w[12 * j + 5] = l2w[5 * j + 0];
        s_w[12 * j + 6] = l2w[5 * j + 1];
        s_w[12 * j + 7] = l2w[5 * j + 2];
        s_w[12 * j + 8] = l2w[5 * j + 3];
        s_w[12 * j + 9] = l2w[5 * j + 4];
        s_w[12 * j + 10] = 0.0f;
        s_w[12 * j + 11] = 0.0f;
    } else if (t < 64) {
        const int u = t - 32;
        if (u < 12) {
            float v;
            if      (u == 0) v = c1w[0];
            else if (u == 1) v = c1w[1];
            else if (u == 2) v = c1b[0];
            else if (u == 3) v = c2w[0];
            else if (u == 4) v = c2w[1];
            else if (u == 5) v = c2b[0];
            else if (u < 11) v = l2b[u - 6];
            else             v = 0.0f;
            s_cb[u] = v;
        }
    }
    __syncthreads();

    const int R0 = blockIdx.x * NT;
    int rows_blk = n - R0; if (rows_blk > NT) rows_blk = NT;

    const int row = R0 + ((t < rows_blk) ? t : 0);   // clamp inactive lanes

    const float c1w0 = s_cb[0], c1w1 = s_cb[1], c1b0 = s_cb[2];
    const float c2w0 = s_cb[3], c2w1 = s_cb[4], c2b0 = s_cb[5];
    const float l2b0 = s_cb[6], l2b1 = s_cb[7], l2b2 = s_cb[8];
    const float l2b3 = s_cb[9], l2b4 = s_cb[10];

    float* my = s_rows + t * CB;

    // ---- load state row ----
    const float* xr = x + (long long)row * NCOLS_IN;
    float2 v0 = *(const float2*)(xr + 0);
    float2 v1 = *(const float2*)(xr + 2);
    float2 v2 = *(const float2*)(xr + 4);
    float2 v3 = *(const float2*)(xr + 6);
    float2 v4 = *(const float2*)(xr + 8);
    float2 v8 = *(const float2*)(xr + 16);
    float s0 = v0.x, s1 = v0.y, s2 = v1.x, s3 = v1.y;
    float s4 = v2.x, s5 = v2.y, s6 = v3.x, s7 = v3.y;
    float s8 = v4.x, s9 = v4.y, s10;
    float s11 = 0.0f, s12 = 0.0f, s13 = 0.0f, s14 = 0.0f, s15 = 0.0f, s16 = 0.0f;
    float s17 = v8.y;

    {
        float d13 = s1 - s3, d24 = s2 - s4;
        s10 = fmaf(d13, d13, d24 * d24);
    }

    // traj0 -> phase-1 slots 0..9 (output cols 18..27)
    my[0] = s10; my[1] = s1; my[2] = s2; my[3] = s3; my[4] = s4;
    my[5] = s5;  my[6] = s6; my[7] = s7; my[8] = s8; my[9] = s17;

    // step body macro-equivalent via lambda
    auto do_step = [&](float* slot) {
        const float f0 = s1, f1 = s2, f2 = s3, f3 = s4, f4 = s9, f5 = s17;

        float h10 = fmaxf(fmaf(c1w1, f1, fmaf(c1w0, f0, c1b0)), 0.0f);
        float h11 = fmaxf(fmaf(c1w1, f2, fmaf(c1w0, f1, c1b0)), 0.0f);
        float h12 = fmaxf(fmaf(c1w1, f3, fmaf(c1w0, f2, c1b0)), 0.0f);
        float h13 = fmaxf(fmaf(c1w1, f4, fmaf(c1w0, f3, c1b0)), 0.0f);
        float h14 = fmaxf(fmaf(c1w1, f5, fmaf(c1w0, f4, c1b0)), 0.0f);

        float h20 = fmaxf(fmaf(c2w1, h11, fmaf(c2w0, h10, c2b0)), 0.0f);
        float h21 = fmaxf(fmaf(c2w1, h12, fmaf(c2w0, h11, c2b0)), 0.0f);
        float h22 = fmaxf(fmaf(c2w1, h13, fmaf(c2w0, h12, c2b0)), 0.0f);
        float h23 = fmaxf(fmaf(c2w1, h14, fmaf(c2w0, h13, c2b0)), 0.0f);

        float p0 = l2b0, p1 = l2b1, p2 = l2b2, p3 = l2b3, p4 = l2b4;

        #pragma unroll 8
        for (int j = 0; j < 32; j++) {
            const float4 wa = *(const float4*)(s_w + 12 * j + 0);
            const float4 wb = *(const float4*)(s_w + 12 * j + 4);
            const float2 wc = *(const float2*)(s_w + 12 * j + 8);
            float h3 = fmaf(h23, wa.w,
                       fmaf(h22, wa.z,
                       fmaf(h21, wa.y,
                       fmaf(h20, wa.x, wb.x))));
            h3 = fmaxf(h3, 0.0f);
            p0 = fmaf(h3, wb.y, p0);
            p1 = fmaf(h3, wb.z, p1);
            p2 = fmaf(h3, wb.w, p2);
            p3 = fmaf(h3, wc.x, p3);
            p4 = fmaf(h3, wc.y, p4);
        }

        p0 = 1.0f / (1.0f + expf(-p0));
        p1 = 1.0f / (1.0f + expf(-p1));
        p2 = 1.0f / (1.0f + expf(-p2));
        p3 = 1.0f / (1.0f + expf(-p3));
        p4 = 1.0f / (1.0f + expf(-p4));

        s5 = p0; s6 = p1; s7 = p2; s8 = p3; s17 = p4;

        const float a = p1 - p0, b = p2 - p0, c = p3 - p0;
        const float d = p2 - p1, e = p3 - p1, f = p3 - p2;
        s11 = a; s12 = b; s13 = c; s14 = d; s15 = e; s16 = f;

        const float dx_c = (c <= 0.0f) ? 0.0f : SPEED;
        const float st_c = (c <= 0.0f) ? 0.0f : 3.0f;
        const float dx_f = (f <= 0.0f) ? 0.0f : SPEED;
        const float st_f = (f <= 0.0f) ? 2.0f : 3.0f;
        const float dx_e = (e <= 0.0f) ? -SPEED : SPEED;
        const float st_e = (e <= 0.0f) ? 1.0f : 3.0f;
        const float dx_b = (b <= 0.0f) ? dx_c : dx_f;
        const float st_b = (b <= 0.0f) ? st_c : st_f;
        const float dx_d = (d <= 0.0f) ? dx_e : dx_f;
        const float st_d = (d <= 0.0f) ? st_e : st_f;
        const float dx   = (a <= 0.0f) ? dx_b : dx_d;
        const float st   = (a <= 0.0f) ? st_b : st_d;

        s1 += dx;
        s9 = st;
        s2 += SPEED;
        s3 += SPEED;
        s0 += 1.0f;
        {
            float d13 = s1 - s3, d24 = s2 - s4;
            s10 = fmaf(d13, d13, d24 * d24);
        }

        slot[0] = s10; slot[1] = s1; slot[2] = s2; slot[3] = s3; slot[4] = s4;
        slot[5] = s5;  slot[6] = s6; slot[7] = s7; slot[8] = s8; slot[9] = s17;
    };

    // Phase 1: steps 0..4 -> slots 10..59 (output cols 18..77)
    #pragma unroll 1
    for (int step = 0; step < 5; step++)
        do_step(my + 10 * (step + 1));

    __syncthreads();
    flush_seg(out, s_rows, R0, rows_blk, 18, 60, t);
    __syncthreads();

    // Phase 2: steps 5..10 -> slots 0..59 (output cols 78..137)
    #pragma unroll 1
    for (int step = 5; step < 11; step++)
        do_step(my + 10 * (step - 5));

    __syncthreads();
    flush_seg(out, s_rows, R0, rows_blk, 78, 60, t);
    __syncthreads();

    // Phase 3: steps 11..14 -> slots 0..39 (output cols 138..177)
    #pragma unroll 1
    for (int step = 11; step < 15; step++)
        do_step(my + 10 * (step - 11));

    // final state -> slots 40..57 (output cols 0..17)
    my[40] = s0;  my[41] = s1;  my[42] = s2;  my[43] = s3;
    my[44] = s4;  my[45] = s5;  my[46] = s6;  my[47] = s7;
    my[48] = s8;  my[49] = s9;  my[50] = s10; my[51] = s11;
    my[52] = s12; my[53] = s13; my[54] = s14; my[55] = s15;
    my[56] = s16; my[57] = s17;

    __syncthreads();
    flush_seg(out, s_rows, R0, rows_blk, 138, 40, t);
    // final-state segment: cols [0,18) from slots 40..57
    {
        const unsigned total = (unsigned)rows_blk * 18;
        for (unsigned idx = t; idx < total; idx += NT) {
            unsigned r = idx / 18;
            unsigned c = idx - r * 18;
            out[(long long)(R0 + r) * NCOLS_OUT + c] = s_rows[r * CB + 40 + c];
        }
    }
}

extern "C" void kernel_launch(void* const* d_in, const int* in_sizes, int n_in,
                              void* d_out, int out_size)
{
    const float* x   = (const float*)d_in[0];
    const float* c1w = (const float*)d_in[1];
    const float* c1b = (const float*)d_in[2];
    const float* c2w = (const float*)d_in[3];
    const float* c2b = (const float*)d_in[4];
    const float* l1w = (const float*)d_in[5];
    const float* l1b = (const float*)d_in[6];
    const float* l2w = (const float*)d_in[7];
    const float* l2b = (const float*)d_in[8];
    float* out = (float*)d_out;

    const int n = in_sizes[0] / NCOLS_IN;
    const int blocks = (n + NT - 1) / NT;
    prog_kernel<<<blocks, NT, SMEM_BYTES>>>(x, c1w, c1b, c2w, c2b,
                                            l1w, l1b, l2w, l2b, out, n);
}

// round 7
// speedup vs baseline: 2.9975x; 1.0147x over previous
#include <cuda_runtime.h>

#define NT 128
#define STEPS 15
#define SPEED 5.0f
#define NCOLS_IN 18
#define NCOLS_OUT 178
#define CB 41                   // 40 staged cols per phase + 1 pad (odd stride)
#define SMEM_BYTES (NT * CB * 4)

template <int NC>
__device__ __forceinline__ void flush_seg(float* __restrict__ out,
                                          const float* __restrict__ stage,
                                          int R0, int rows_blk, int base_col, int t)
{
    const unsigned total = (unsigned)rows_blk * NC;
    for (unsigned idx = t; idx < total; idx += NT) {
        unsigned r = idx / NC;             // compile-time NC -> mul/shift
        unsigned c = idx - r * NC;
        out[(long long)(R0 + r) * NCOLS_OUT + base_col + c] = stage[r * CB + c];
    }
}

__global__ void __launch_bounds__(NT) prog_kernel(
    const float* __restrict__ x,
    const float* __restrict__ c1w, const float* __restrict__ c1b,
    const float* __restrict__ c2w, const float* __restrict__ c2b,
    const float* __restrict__ l1w, const float* __restrict__ l1b,
    const float* __restrict__ l2w, const float* __restrict__ l2b,
    float* __restrict__ out, int n)
{
    extern __shared__ float s_rows[];   // NT * CB staging

    // Pair-packed weights: 16 blocks of 20 floats (80B, 16B-aligned).
    // Block q holds neurons j0=2q, j1=2q+1:
    //  [0..3]  l1w^T[j0]   [4] l1b[j0]  [5..9]  l2w[j0][0..4]
    //  [10..13] l1w^T[j1] [14] l1b[j1] [15..19] l2w[j1][0..4]
    __shared__ float s_w[16 * 20];
    __shared__ float s_cb[12];

    const int t = threadIdx.x;
    if (t < 32) {
        const int j = t;
        const int base = 20 * (j >> 1) + 10 * (j & 1);
        s_w[base + 0] = l1w[0 * 32 + j];
        s_w[base + 1] = l1w[1 * 32 + j];
        s_w[base + 2] = l1w[2 * 32 + j];
        s_w[base + 3] = l1w[3 * 32 + j];
        s_w[base + 4] = l1b[j];
        s_w[base + 5] = l2w[5 * j + 0];
        s_w[base + 6] = l2w[5 * j + 1];
        s_w[base + 7] = l2w[5 * j + 2];
        s_w[base + 8] = l2w[5 * j + 3];
        s_w[base + 9] = l2w[5 * j + 4];
    } else if (t < 64) {
        const int u = t - 32;
        if (u < 12) {
            float v;
            if      (u == 0) v = c1w[0];
            else if (u == 1) v = c1w[1];
            else if (u == 2) v = c1b[0];
            else if (u == 3) v = c2w[0];
            else if (u == 4) v = c2w[1];
            else if (u == 5) v = c2b[0];
            else if (u < 11) v = l2b[u - 6];
            else             v = 0.0f;
            s_cb[u] = v;
        }
    }
    __syncthreads();

    const int R0 = blockIdx.x * NT;
    int rows_blk = n - R0; if (rows_blk > NT) rows_blk = NT;

    const int row = R0 + ((t < rows_blk) ? t : 0);   // clamp inactive lanes

    const float c1w0 = s_cb[0], c1w1 = s_cb[1], c1b0 = s_cb[2];
    const float c2w0 = s_cb[3], c2w1 = s_cb[4], c2b0 = s_cb[5];
    const float l2b0 = s_cb[6], l2b1 = s_cb[7], l2b2 = s_cb[8];
    const float l2b3 = s_cb[9], l2b4 = s_cb[10];

    float* my = s_rows + t * CB;

    // ---- load state row ----
    const float* xr = x + (long long)row * NCOLS_IN;
    float2 v0 = *(const float2*)(xr + 0);
    float2 v1 = *(const float2*)(xr + 2);
    float2 v2 = *(const float2*)(xr + 4);
    float2 v3 = *(const float2*)(xr + 6);
    float2 v4 = *(const float2*)(xr + 8);
    float2 v8 = *(const float2*)(xr + 16);
    float s0 = v0.x, s1 = v0.y, s2 = v1.x, s3 = v1.y;
    float s4 = v2.x, s5 = v2.y, s6 = v3.x, s7 = v3.y;
    float s8 = v4.x, s9 = v4.y, s10;
    float s11 = 0.0f, s12 = 0.0f, s13 = 0.0f, s14 = 0.0f, s15 = 0.0f, s16 = 0.0f;
    float s17 = v8.y;

    {
        float d13 = s1 - s3, d24 = s2 - s4;
        s10 = fmaf(d13, d13, d24 * d24);
    }

    auto do_step = [&](float* slot) {
        const float f0 = s1, f1 = s2, f2 = s3, f3 = s4, f4 = s9, f5 = s17;

        float h10 = fmaxf(fmaf(c1w1, f1, fmaf(c1w0, f0, c1b0)), 0.0f);
        float h11 = fmaxf(fmaf(c1w1, f2, fmaf(c1w0, f1, c1b0)), 0.0f);
        float h12 = fmaxf(fmaf(c1w1, f3, fmaf(c1w0, f2, c1b0)), 0.0f);
        float h13 = fmaxf(fmaf(c1w1, f4, fmaf(c1w0, f3, c1b0)), 0.0f);
        float h14 = fmaxf(fmaf(c1w1, f5, fmaf(c1w0, f4, c1b0)), 0.0f);

        float h20 = fmaxf(fmaf(c2w1, h11, fmaf(c2w0, h10, c2b0)), 0.0f);
        float h21 = fmaxf(fmaf(c2w1, h12, fmaf(c2w0, h11, c2b0)), 0.0f);
        float h22 = fmaxf(fmaf(c2w1, h13, fmaf(c2w0, h12, c2b0)), 0.0f);
        float h23 = fmaxf(fmaf(c2w1, h14, fmaf(c2w0, h13, c2b0)), 0.0f);

        float p0 = l2b0, p1 = l2b1, p2 = l2b2, p3 = l2b3, p4 = l2b4;

        #pragma unroll 4
        for (int q = 0; q < 16; q++) {
            const float4 a0 = *(const float4*)(s_w + 20 * q + 0);
            const float4 a1 = *(const float4*)(s_w + 20 * q + 4);
            const float4 a2 = *(const float4*)(s_w + 20 * q + 8);
            const float4 a3 = *(const float4*)(s_w + 20 * q + 12);
            const float4 a4 = *(const float4*)(s_w + 20 * q + 16);

            float h3a = fmaf(h23, a0.w,
                        fmaf(h22, a0.z,
                        fmaf(h21, a0.y,
                        fmaf(h20, a0.x, a1.x))));
            h3a = fmaxf(h3a, 0.0f);
            p0 = fmaf(h3a, a1.y, p0);
            p1 = fmaf(h3a, a1.z, p1);
            p2 = fmaf(h3a, a1.w, p2);
            p3 = fmaf(h3a, a2.x, p3);
            p4 = fmaf(h3a, a2.y, p4);

            float h3b = fmaf(h23, a3.y,
                        fmaf(h22, a3.x,
                        fmaf(h21, a2.w,
                        fmaf(h20, a2.z, a3.z))));
            h3b = fmaxf(h3b, 0.0f);
            p0 = fmaf(h3b, a3.w, p0);
            p1 = fmaf(h3b, a4.x, p1);
            p2 = fmaf(h3b, a4.y, p2);
            p3 = fmaf(h3b, a4.z, p3);
            p4 = fmaf(h3b, a4.w, p4);
        }

        p0 = 1.0f / (1.0f + expf(-p0));
        p1 = 1.0f / (1.0f + expf(-p1));
        p2 = 1.0f / (1.0f + expf(-p2));
        p3 = 1.0f / (1.0f + expf(-p3));
        p4 = 1.0f / (1.0f + expf(-p4));

        s5 = p0; s6 = p1; s7 = p2; s8 = p3; s17 = p4;

        const float a = p1 - p0, b = p2 - p0, c = p3 - p0;
        const float d = p2 - p1, e = p3 - p1, f = p3 - p2;
        s11 = a; s12 = b; s13 = c; s14 = d; s15 = e; s16 = f;

        const float dx_c = (c <= 0.0f) ? 0.0f : SPEED;
        const float st_c = (c <= 0.0f) ? 0.0f : 3.0f;
        const float dx_f = (f <= 0.0f) ? 0.0f : SPEED;
        const float st_f = (f <= 0.0f) ? 2.0f : 3.0f;
        const float dx_e = (e <= 0.0f) ? -SPEED : SPEED;
        const float st_e = (e <= 0.0f) ? 1.0f : 3.0f;
        const float dx_b = (b <= 0.0f) ? dx_c : dx_f;
        const float st_b = (b <= 0.0f) ? st_c : st_f;
        const float dx_d = (d <= 0.0f) ? dx_e : dx_f;
        const float st_d = (d <= 0.0f) ? st_e : st_f;
        const float dx   = (a <= 0.0f) ? dx_b : dx_d;
        const float st   = (a <= 0.0f) ? st_b : st_d;

        s1 += dx;
        s9 = st;
        s2 += SPEED;
        s3 += SPEED;
        s0 += 1.0f;
        {
            float d13 = s1 - s3, d24 = s2 - s4;
            s10 = fmaf(d13, d13, d24 * d24);
        }

        slot[0] = s10; slot[1] = s1; slot[2] = s2; slot[3] = s3; slot[4] = s4;
        slot[5] = s5;  slot[6] = s6; slot[7] = s7; slot[8] = s8; slot[9] = s17;
    };

    // Phase 1: traj0 (slots 0..9) + steps 0..2 (slots 10..39) -> cols 18..57
    my[0] = s10; my[1] = s1; my[2] = s2; my[3] = s3; my[4] = s4;
    my[5] = s5;  my[6] = s6; my[7] = s7; my[8] = s8; my[9] = s17;
    #pragma unroll 1
    for (int step = 0; step < 3; step++)
        do_step(my + 10 * (step + 1));
    __syncthreads();
    flush_seg<40>(out, s_rows, R0, rows_blk, 18, t);
    __syncthreads();

    // Phase 2: steps 3..6 -> cols 58..97
    #pragma unroll 1
    for (int step = 3; step < 7; step++)
        do_step(my + 10 * (step - 3));
    __syncthreads();
    flush_seg<40>(out, s_rows, R0, rows_blk, 58, t);
    __syncthreads();

    // Phase 3: steps 7..10 -> cols 98..137
    #pragma unroll 1
    for (int step = 7; step < 11; step++)
        do_step(my + 10 * (step - 7));
    __syncthreads();
    flush_seg<40>(out, s_rows, R0, rows_blk, 98, t);
    __syncthreads();

    // Phase 4: steps 11..14 -> cols 138..177
    #pragma unroll 1
    for (int step = 11; step < 15; step++)
        do_step(my + 10 * (step - 11));
    __syncthreads();
    flush_seg<40>(out, s_rows, R0, rows_blk, 138, t);
    __syncthreads();

    // Phase 5: final state (18 cols) -> cols 0..17
    my[0] = s0;  my[1] = s1;  my[2] = s2;  my[3] = s3;
    my[4] = s4;  my[5] = s5;  my[6] = s6;  my[7] = s7;
    my[8] = s8;  my[9] = s9;  my[10] = s10; my[11] = s11;
    my[12] = s12; my[13] = s13; my[14] = s14; my[15] = s15;
    my[16] = s16; my[17] = s17;
    __syncthreads();
    flush_seg<18>(out, s_rows, R0, rows_blk, 0, t);
}

extern "C" void kernel_launch(void* const* d_in, const int* in_sizes, int n_in,
                              void* d_out, int out_size)
{
    const float* x   = (const float*)d_in[0];
    const float* c1w = (const float*)d_in[1];
    const float* c1b = (const float*)d_in[2];
    const float* c2w = (const float*)d_in[3];
    const float* c2b = (const float*)d_in[4];
    const float* l1w = (const float*)d_in[5];
    const float* l1b = (const float*)d_in[6];
    const float* l2w = (const float*)d_in[7];
    const float* l2b = (const float*)d_in[8];
    float* out = (float*)d_out;

    const int n = in_sizes[0] / NCOLS_IN;
    const int blocks = (n + NT - 1) / NT;
    prog_kernel<<<blocks, NT, SMEM_BYTES>>>(x, c1w, c1b, c2w, c2b,
                                            l1w, l1b, l2w, l2b, out, n);
}

// round 8
// speedup vs baseline: 3.4048x; 1.1359x over previous
#include <cuda_runtime.h>

#define NT 128
#define RPC 256                 // rows per CTA (2 per thread)
#define STEPS 15
#define SPEED 5.0f
#define NCOLS_IN 18
#define NCOLS_OUT 178
#define CB 42                   // staged cols per row (40 used) ; even -> 8B aligned slots
#define SMEM_BYTES (RPC * CB * 4)

template <int NC>
__device__ __forceinline__ void flush2(float* __restrict__ out,
                                       const float* __restrict__ stage,
                                       int R0, int rows_blk, int base_col, int t)
{
    constexpr int NC2 = NC / 2;          // NC even
    const unsigned total = (unsigned)rows_blk * NC2;
    for (unsigned idx = t; idx < total; idx += NT) {
        unsigned r = idx / NC2;
        unsigned k = idx - r * NC2;
        float2 v = *(const float2*)(stage + r * CB + 2 * k);
        *(float2*)(out + (long long)(R0 + r) * NCOLS_OUT + base_col + 2 * k) = v;
    }
}

__global__ void __launch_bounds__(NT) prog_kernel(
    const float* __restrict__ x,
    const float* __restrict__ c1w, const float* __restrict__ c1b,
    const float* __restrict__ c2w, const float* __restrict__ c2b,
    const float* __restrict__ l1w, const float* __restrict__ l1b,
    const float* __restrict__ l2w, const float* __restrict__ l2b,
    float* __restrict__ out, int n)
{
    extern __shared__ float s_rows[];   // RPC * CB staging

    // Pair-packed weights: 16 blocks of 20 floats (80B, 16B-aligned).
    __shared__ float s_w[16 * 20];
    __shared__ float s_cb[12];

    const int t = threadIdx.x;
    if (t < 32) {
        const int j = t;
        const int base = 20 * (j >> 1) + 10 * (j & 1);
        s_w[base + 0] = l1w[0 * 32 + j];
        s_w[base + 1] = l1w[1 * 32 + j];
        s_w[base + 2] = l1w[2 * 32 + j];
        s_w[base + 3] = l1w[3 * 32 + j];
        s_w[base + 4] = l1b[j];
        s_w[base + 5] = l2w[5 * j + 0];
        s_w[base + 6] = l2w[5 * j + 1];
        s_w[base + 7] = l2w[5 * j + 2];
        s_w[base + 8] = l2w[5 * j + 3];
        s_w[base + 9] = l2w[5 * j + 4];
    } else if (t < 64) {
        const int u = t - 32;
        if (u < 12) {
            float v;
            if      (u == 0) v = c1w[0];
            else if (u == 1) v = c1w[1];
            else if (u == 2) v = c1b[0];
            else if (u == 3) v = c2w[0];
            else if (u == 4) v = c2w[1];
            else if (u == 5) v = c2b[0];
            else if (u < 11) v = l2b[u - 6];
            else             v = 0.0f;
            s_cb[u] = v;
        }
    }
    __syncthreads();

    const int R0 = blockIdx.x * RPC;
    int rows_blk = n - R0; if (rows_blk > RPC) rows_blk = RPC;

    const float c1w0 = s_cb[0], c1w1 = s_cb[1], c1b0 = s_cb[2];
    const float c2w0 = s_cb[3], c2w1 = s_cb[4], c2b0 = s_cb[5];
    const float l2b0 = s_cb[6], l2b1 = s_cb[7], l2b2 = s_cb[8];
    const float l2b3 = s_cb[9], l2b4 = s_cb[10];

    // two rows per thread: local row ids t and t+NT
    float s0[2], s1[2], s2[2], s3[2], s4[2], s5[2], s6[2], s7[2], s8[2],
          s9[2], s10[2], s11[2], s12[2], s13[2], s14[2], s15[2], s16[2], s17[2];
    float* my[2];

    #pragma unroll
    for (int r = 0; r < 2; r++) {
        const int lr = t + r * NT;                       // local row in CTA
        const int row = R0 + ((lr < rows_blk) ? lr : 0); // clamp inactive
        my[r] = s_rows + lr * CB;
        const float* xr = x + (long long)row * NCOLS_IN;
        float2 v0 = *(const float2*)(xr + 0);
        float2 v1 = *(const float2*)(xr + 2);
        float2 v2 = *(const float2*)(xr + 4);
        float2 v3 = *(const float2*)(xr + 6);
        float2 v4 = *(const float2*)(xr + 8);
        float2 v8 = *(const float2*)(xr + 16);
        s0[r] = v0.x; s1[r] = v0.y; s2[r] = v1.x; s3[r] = v1.y;
        s4[r] = v2.x; s5[r] = v2.y; s6[r] = v3.x; s7[r] = v3.y;
        s8[r] = v4.x; s9[r] = v4.y; s17[r] = v8.y;
        float d13 = s1[r] - s3[r], d24 = s2[r] - s4[r];
        s10[r] = fmaf(d13, d13, d24 * d24);
        s11[r] = s12[r] = s13[r] = s14[r] = s15[r] = s16[r] = 0.0f;
    }

    auto stash = [&](int r, float* slot) {
        *(float2*)(slot + 0) = make_float2(s10[r], s1[r]);
        *(float2*)(slot + 2) = make_float2(s2[r], s3[r]);
        *(float2*)(slot + 4) = make_float2(s4[r], s5[r]);
        *(float2*)(slot + 6) = make_float2(s6[r], s7[r]);
        *(float2*)(slot + 8) = make_float2(s8[r], s17[r]);
    };

    auto do_step = [&](int slot_off) {
        float h20[2], h21[2], h22[2], h23[2];
        float p0[2], p1[2], p2[2], p3[2], p4[2];

        #pragma unroll
        for (int r = 0; r < 2; r++) {
            const float f0 = s1[r], f1 = s2[r], f2 = s3[r], f3 = s4[r],
                        f4 = s9[r], f5 = s17[r];
            float h10 = fmaxf(fmaf(c1w1, f1, fmaf(c1w0, f0, c1b0)), 0.0f);
            float h11 = fmaxf(fmaf(c1w1, f2, fmaf(c1w0, f1, c1b0)), 0.0f);
            float h12 = fmaxf(fmaf(c1w1, f3, fmaf(c1w0, f2, c1b0)), 0.0f);
            float h13 = fmaxf(fmaf(c1w1, f4, fmaf(c1w0, f3, c1b0)), 0.0f);
            float h14 = fmaxf(fmaf(c1w1, f5, fmaf(c1w0, f4, c1b0)), 0.0f);
            h20[r] = fmaxf(fmaf(c2w1, h11, fmaf(c2w0, h10, c2b0)), 0.0f);
            h21[r] = fmaxf(fmaf(c2w1, h12, fmaf(c2w0, h11, c2b0)), 0.0f);
            h22[r] = fmaxf(fmaf(c2w1, h13, fmaf(c2w0, h12, c2b0)), 0.0f);
            h23[r] = fmaxf(fmaf(c2w1, h14, fmaf(c2w0, h13, c2b0)), 0.0f);
            p0[r] = l2b0; p1[r] = l2b1; p2[r] = l2b2; p3[r] = l2b3; p4[r] = l2b4;
        }

        #pragma unroll 8
        for (int q = 0; q < 16; q++) {
            const float4 a0 = *(const float4*)(s_w + 20 * q + 0);
            const float4 a1 = *(const float4*)(s_w + 20 * q + 4);
            const float4 a2 = *(const float4*)(s_w + 20 * q + 8);
            const float4 a3 = *(const float4*)(s_w + 20 * q + 12);
            const float4 a4 = *(const float4*)(s_w + 20 * q + 16);

            #pragma unroll
            for (int r = 0; r < 2; r++) {
                float h3a = fmaf(h23[r], a0.w,
                            fmaf(h22[r], a0.z,
                            fmaf(h21[r], a0.y,
                            fmaf(h20[r], a0.x, a1.x))));
                h3a = fmaxf(h3a, 0.0f);
                p0[r] = fmaf(h3a, a1.y, p0[r]);
                p1[r] = fmaf(h3a, a1.z, p1[r]);
                p2[r] = fmaf(h3a, a1.w, p2[r]);
                p3[r] = fmaf(h3a, a2.x, p3[r]);
                p4[r] = fmaf(h3a, a2.y, p4[r]);

                float h3b = fmaf(h23[r], a3.y,
                            fmaf(h22[r], a3.x,
                            fmaf(h21[r], a2.w,
                            fmaf(h20[r], a2.z, a3.z))));
                h3b = fmaxf(h3b, 0.0f);
                p0[r] = fmaf(h3b, a3.w, p0[r]);
                p1[r] = fmaf(h3b, a4.x, p1[r]);
                p2[r] = fmaf(h3b, a4.y, p2[r]);
                p3[r] = fmaf(h3b, a4.z, p3[r]);
                p4[r] = fmaf(h3b, a4.w, p4[r]);
            }
        }

        #pragma unroll
        for (int r = 0; r < 2; r++) {
            float q0 = 1.0f / (1.0f + expf(-p0[r]));
            float q1 = 1.0f / (1.0f + expf(-p1[r]));
            float q2 = 1.0f / (1.0f + expf(-p2[r]));
            float q3 = 1.0f / (1.0f + expf(-p3[r]));
            float q4 = 1.0f / (1.0f + expf(-p4[r]));

            s5[r] = q0; s6[r] = q1; s7[r] = q2; s8[r] = q3; s17[r] = q4;

            const float a = q1 - q0, b = q2 - q0, c = q3 - q0;
            const float d = q2 - q1, e = q3 - q1, f = q3 - q2;
            s11[r] = a; s12[r] = b; s13[r] = c;
            s14[r] = d; s15[r] = e; s16[r] = f;

            const float dx_c = (c <= 0.0f) ? 0.0f : SPEED;
            const float st_c = (c <= 0.0f) ? 0.0f : 3.0f;
            const float dx_f = (f <= 0.0f) ? 0.0f : SPEED;
            const float st_f = (f <= 0.0f) ? 2.0f : 3.0f;
            const float dx_e = (e <= 0.0f) ? -SPEED : SPEED;
            const float st_e = (e <= 0.0f) ? 1.0f : 3.0f;
            const float dx_b = (b <= 0.0f) ? dx_c : dx_f;
            const float st_b = (b <= 0.0f) ? st_c : st_f;
            const float dx_d = (d <= 0.0f) ? dx_e : dx_f;
            const float st_d = (d <= 0.0f) ? st_e : st_f;
            const float dx   = (a <= 0.0f) ? dx_b : dx_d;
            const float st   = (a <= 0.0f) ? st_b : st_d;

            s1[r] += dx;
            s9[r] = st;
            s2[r] += SPEED;
            s3[r] += SPEED;
            s0[r] += 1.0f;
            float d13 = s1[r] - s3[r], d24 = s2[r] - s4[r];
            s10[r] = fmaf(d13, d13, d24 * d24);

            stash(r, my[r] + slot_off);
        }
    };

    // Phase 1: traj0 (slots 0..9) + steps 0..2 -> cols 18..57
    #pragma unroll
    for (int r = 0; r < 2; r++) stash(r, my[r]);
    #pragma unroll 1
    for (int step = 0; step < 3; step++)
        do_step(10 * (step + 1));
    __syncthreads();
    flush2<40>(out, s_rows, R0, rows_blk, 18, t);
    __syncthreads();

    // Phase 2: steps 3..6 -> cols 58..97
    #pragma unroll 1
    for (int step = 3; step < 7; step++)
        do_step(10 * (step - 3));
    __syncthreads();
    flush2<40>(out, s_rows, R0, rows_blk, 58, t);
    __syncthreads();

    // Phase 3: steps 7..10 -> cols 98..137
    #pragma unroll 1
    for (int step = 7; step < 11; step++)
        do_step(10 * (step - 7));
    __syncthreads();
    flush2<40>(out, s_rows, R0, rows_blk, 98, t);
    __syncthreads();

    // Phase 4: steps 11..14 -> cols 138..177
    #pragma unroll 1
    for (int step = 11; step < 15; step++)
        do_step(10 * (step - 11));
    __syncthreads();
    flush2<40>(out, s_rows, R0, rows_blk, 138, t);
    __syncthreads();

    // Phase 5: final state (18 cols) -> cols 0..17
    #pragma unroll
    for (int r = 0; r < 2; r++) {
        float* m = my[r];
        *(float2*)(m + 0)  = make_float2(s0[r], s1[r]);
        *(float2*)(m + 2)  = make_float2(s2[r], s3[r]);
        *(float2*)(m + 4)  = make_float2(s4[r], s5[r]);
        *(float2*)(m + 6)  = make_float2(s6[r], s7[r]);
        *(float2*)(m + 8)  = make_float2(s8[r], s9[r]);
        *(float2*)(m + 10) = make_float2(s10[r], s11[r]);
        *(float2*)(m + 12) = make_float2(s12[r], s13[r]);
        *(float2*)(m + 14) = make_float2(s14[r], s15[r]);
        *(float2*)(m + 16) = make_float2(s16[r], s17[r]);
    }
    __syncthreads();
    flush2<18>(out, s_rows, R0, rows_blk, 0, t);
}

extern "C" void kernel_launch(void* const* d_in, const int* in_sizes, int n_in,
                              void* d_out, int out_size)
{
    const float* x   = (const float*)d_in[0];
    const float* c1w = (const float*)d_in[1];
    const float* c1b = (const float*)d_in[2];
    const float* c2w = (const float*)d_in[3];
    const float* c2b = (const float*)d_in[4];
    const float* l1w = (const float*)d_in[5];
    const float* l1b = (const float*)d_in[6];
    const float* l2w = (const float*)d_in[7];
    const float* l2b = (const float*)d_in[8];
    float* out = (float*)d_out;

    const int n = in_sizes[0] / NCOLS_IN;
    const int blocks = (n + RPC - 1) / RPC;
    prog_kernel<<<blocks, NT, SMEM_BYTES>>>(x, c1w, c1b, c2w, c2b,
                                            l1w, l1b, l2w, l2b, out, n);
}